// round 1
// baseline (speedup 1.0000x reference)
#include <cuda_runtime.h>
#include <cuda_bf16.h>
#include <math_constants.h>

// Problem constants (fixed by the benchmark)
#define BB 2
#define LL 2048
#define HH 8
#define DD 64
#define UU 80
#define SS 80
#define BHN (BB*HH)

// Scratch (device globals; no allocations allowed)
__device__ float g_M[BB*HH*LL];     // sparsity measure M[b,h,l]
__device__ int   g_nw[BHN];          // number of winner rows per (b,h)
__device__ int   g_wl[BHN*UU];       // winner: source token index l (= M_top[u])
__device__ int   g_wj[BHN*UU];       // winner: output slot j (clipped index)

// ---------------------------------------------------------------------------
// Kernel 1: sampled scores -> M[b,h,l] = max_s(QK_s) - sum_s(QK_s)/L
// One warp per (b,h,l) row. 4 groups of 8 lanes, each group computes one
// sampled dot product per iteration (8 lanes x 8 floats = 64-d dot).
// K row loads are 4 x 128B contiguous segments per LDG.128 -> good coalescing.
// ---------------------------------------------------------------------------
__global__ void k_sample(const float* __restrict__ Q, const float* __restrict__ K,
                         const int* __restrict__ idx) {
    int gw = (blockIdx.x * blockDim.x + threadIdx.x) >> 5;
    if (gw >= BB*HH*LL) return;
    int lane = threadIdx.x & 31;
    int l  = gw & (LL-1);
    int bh = gw >> 11;
    int b = bh >> 3, h = bh & 7;
    int grp = lane >> 3;   // 0..3 : which sample within the 4-wide iteration
    int lg  = lane & 7;    // 0..7 : which 8-float chunk of d

    const float* qrow = Q + (((size_t)b*LL + l)*HH + h)*DD;
    float4 q0 = *(const float4*)(qrow + lg*8);
    float4 q1 = *(const float4*)(qrow + lg*8 + 4);

    const int* irow = idx + l*SS;
    float vmax = -CUDART_INF_F, vsum = 0.f;

    #pragma unroll 5
    for (int it = 0; it < SS/4; ++it) {
        int j = irow[it*4 + grp];
        const float* krow = K + (((size_t)b*LL + j)*HH + h)*DD + lg*8;
        float4 k0 = *(const float4*)(krow);
        float4 k1 = *(const float4*)(krow + 4);
        float p = q0.x*k0.x + q0.y*k0.y + q0.z*k0.z + q0.w*k0.w
                + q1.x*k1.x + q1.y*k1.y + q1.z*k1.z + q1.w*k1.w;
        // butterfly within 8-lane group -> all 8 lanes hold the full dot
        p += __shfl_xor_sync(0xffffffffu, p, 4);
        p += __shfl_xor_sync(0xffffffffu, p, 2);
        p += __shfl_xor_sync(0xffffffffu, p, 1);
        vmax = fmaxf(vmax, p);
        vsum += p;
    }
    // combine the 4 groups (each lane of a group holds identical stats)
    vmax = fmaxf(vmax, __shfl_xor_sync(0xffffffffu, vmax, 8));
    vmax = fmaxf(vmax, __shfl_xor_sync(0xffffffffu, vmax, 16));
    vsum += __shfl_xor_sync(0xffffffffu, vsum, 8);
    vsum += __shfl_xor_sync(0xffffffffu, vsum, 16);
    if (lane == 0) g_M[gw] = vmax - vsum * (1.0f/(float)LL);
}

// ---------------------------------------------------------------------------
// Kernel 2: per-(b,h) top-80 of M (iterative argmax, ties -> smaller index,
// matching jax.lax.top_k), then replay the clipped scatter (last write wins)
// to build the compacted winner list: only these rows need real attention.
// ---------------------------------------------------------------------------
__global__ void k_topk() {
    int bh = blockIdx.x;
    __shared__ float sm[LL];
    __shared__ float rv[8];
    __shared__ int   ri[8];
    __shared__ int   stop[UU];
    __shared__ int   win[UU];
    int t = threadIdx.x, lane = t & 31, warp = t >> 5;

    for (int i = t; i < LL; i += 256) sm[i] = g_M[bh*LL + i];
    __syncthreads();

    for (int u = 0; u < UU; ++u) {
        float best = -CUDART_INF_F; int bi = LL;
        for (int i = t; i < LL; i += 256) {
            float v = sm[i];
            if (v > best) { best = v; bi = i; }  // strict > keeps smallest i
        }
        #pragma unroll
        for (int o = 16; o; o >>= 1) {
            float ov = __shfl_xor_sync(0xffffffffu, best, o);
            int   oi = __shfl_xor_sync(0xffffffffu, bi, o);
            if (ov > best || (ov == best && oi < bi)) { best = ov; bi = oi; }
        }
        if (lane == 0) { rv[warp] = best; ri[warp] = bi; }
        __syncthreads();
        if (t == 0) {
            float m = rv[0]; int mi = ri[0];
            for (int w = 1; w < 8; ++w)
                if (rv[w] > m || (rv[w] == m && ri[w] < mi)) { m = rv[w]; mi = ri[w]; }
            stop[u] = mi;
            sm[mi] = -CUDART_INF_F;
        }
        __syncthreads();
    }

    if (t < UU) win[t] = -1;
    __syncthreads();
    if (t == 0) {
        // replay scatter in u-order: clipped slot, last write wins
        for (int u = 0; u < UU; ++u) { int jj = min(stop[u], UU-1); win[jj] = u; }
        int n = 0;
        for (int jj = 0; jj < UU; ++jj) {
            if (win[jj] >= 0) {
                g_wl[bh*UU + n] = stop[win[jj]];
                g_wj[bh*UU + n] = jj;
                n++;
            }
        }
        g_nw[bh] = n;
    }
}

// ---------------------------------------------------------------------------
// Kernel 3: V_mean per (b,h), broadcast-fill ALL 80 output rows with it.
// Winner rows are overwritten by k_attn afterwards (stream-ordered).
// Output layout: out[b][j][h][d] (B, u, H, D).
// ---------------------------------------------------------------------------
__global__ void k_vmean_fill(const float* __restrict__ V, float* __restrict__ out) {
    int bh = blockIdx.x; int b = bh >> 3, h = bh & 7;
    int t = threadIdx.x;
    int grp = t >> 6, d = t & 63;
    __shared__ float ac[4][64];
    float s = 0.f;
    for (int k = grp; k < LL; k += 4)
        s += V[(((size_t)b*LL + k)*HH + h)*DD + d];
    ac[grp][d] = s;
    __syncthreads();
    if (t < 64) {
        float m = (ac[0][t] + ac[1][t] + ac[2][t] + ac[3][t]) * (1.0f/(float)LL);
        for (int j = 0; j < UU; ++j)
            out[(((size_t)b*UU + j)*HH + h)*DD + t] = m;
    }
}

// ---------------------------------------------------------------------------
// Kernel 4: full softmax attention, but ONLY for winner rows (~4 per bh).
// One block per (bh, winner slot); blocks past g_nw exit immediately.
// ---------------------------------------------------------------------------
__global__ void k_attn(const float* __restrict__ Q, const float* __restrict__ K,
                       const float* __restrict__ V, float* __restrict__ out) {
    int bh = blockIdx.x;
    if ((int)blockIdx.y >= g_nw[bh]) return;
    int b = bh >> 3, h = bh & 7;
    int l = g_wl[bh*UU + blockIdx.y];
    int j = g_wj[bh*UU + blockIdx.y];

    __shared__ float p[LL];
    __shared__ float q[DD];
    __shared__ float red[8];
    __shared__ float ac[4][64];
    int t = threadIdx.x, lane = t & 31, warp = t >> 5;

    if (t < DD) q[t] = Q[(((size_t)b*LL + l)*HH + h)*DD + t];
    __syncthreads();
    float q0 = q[lane*2], q1 = q[lane*2+1];

    // scores: each warp handles keys k = warp, warp+8, ... (coalesced 256B row)
    float lmax = -CUDART_INF_F;
    for (int k = warp; k < LL; k += 8) {
        float2 kv = *(const float2*)(K + (((size_t)b*LL + k)*HH + h)*DD + lane*2);
        float s = q0*kv.x + q1*kv.y;
        #pragma unroll
        for (int o = 16; o; o >>= 1) s += __shfl_xor_sync(0xffffffffu, s, o);
        s *= 0.125f;                 // 1/sqrt(64)
        if (lane == 0) p[k] = s;
        lmax = fmaxf(lmax, s);
    }
    if (lane == 0) red[warp] = lmax;
    __syncthreads();                 // also publishes p[]
    if (t == 0) { float m = red[0]; for (int w = 1; w < 8; ++w) m = fmaxf(m, red[w]); red[0] = m; }
    __syncthreads();
    float m = red[0];
    __syncthreads();                 // everyone has read red[0] before it is reused

    float ls = 0.f;
    for (int i = t; i < LL; i += 256) { float e = __expf(p[i] - m); p[i] = e; ls += e; }
    #pragma unroll
    for (int o = 16; o; o >>= 1) ls += __shfl_xor_sync(0xffffffffu, ls, o);
    if (lane == 0) red[warp] = ls;
    __syncthreads();                 // publishes exp'd p[] and warp sums
    float inv = 1.0f / (red[0]+red[1]+red[2]+red[3]+red[4]+red[5]+red[6]+red[7]);

    // PV: 4 key-groups x 64 d-threads, coalesced V reads
    int grp = t >> 6, d = t & 63;
    float acc = 0.f;
    for (int k = grp; k < LL; k += 4)
        acc += p[k] * V[(((size_t)b*LL + k)*HH + h)*DD + d];
    ac[grp][d] = acc;
    __syncthreads();
    if (t < 64) {
        float v = (ac[0][t] + ac[1][t] + ac[2][t] + ac[3][t]) * inv;
        out[(((size_t)b*UU + j)*HH + h)*DD + t] = v;
    }
}

// ---------------------------------------------------------------------------
extern "C" void kernel_launch(void* const* d_in, const int* in_sizes, int n_in,
                              void* d_out, int out_size) {
    const float* Q   = (const float*)d_in[0];
    const float* K   = (const float*)d_in[1];
    const float* V   = (const float*)d_in[2];
    const int*   idx = (const int*)d_in[3];
    float* out = (float*)d_out;

    k_sample<<<(BB*HH*LL)/8, 256>>>(Q, K, idx);   // 4096 blocks, 1 warp/row
    k_topk<<<BHN, 256>>>();
    k_vmean_fill<<<BHN, 256>>>(V, out);
    dim3 ga(BHN, UU);
    k_attn<<<ga, 256>>>(Q, K, V, out);
}

// round 2
// speedup vs baseline: 1.3700x; 1.3700x over previous
#include <cuda_runtime.h>
#include <cuda_bf16.h>
#include <math_constants.h>

// Problem constants (fixed by the benchmark)
#define BB 2
#define LL 2048
#define HH 8
#define DD 64
#define UU 80
#define SS 80
#define BHN (BB*HH)
#define SPLIT 16
#define CHUNK (LL/SPLIT)      // 128 keys per split block
#define VSPLIT 8
#define VCHUNK (LL/VSPLIT)    // 256 keys per vmean split

// Scratch (device globals; no allocations allowed)
__device__ float g_M[BB*HH*LL];          // sparsity measure M[b,h,l]
__device__ int   g_nw[BHN];              // winners per (b,h)
__device__ int   g_wl[BHN*UU];           // winner: source token l
__device__ int   g_wj[BHN*UU];           // winner: output slot j
__device__ float g_pmax[BHN*UU*SPLIT];   // split-softmax partial max
__device__ float g_psum[BHN*UU*SPLIT];   // split-softmax partial sum(exp)
__device__ float g_pv  [BHN*UU*SPLIT*DD];// split partial (unnormalized) PV
__device__ float g_vpart[BHN*VSPLIT*DD]; // V partial sums

// ---------------------------------------------------------------------------
// Kernel 1: sampled scores -> M[b,h,l] = max_s(QK_s) - sum_s(QK_s)/L
// One warp per (b,h,l); 4 groups of 8 lanes, one sampled dot per group/iter.
// ---------------------------------------------------------------------------
__global__ void k_sample(const float* __restrict__ Q, const float* __restrict__ K,
                         const int* __restrict__ idx) {
    int gw = (blockIdx.x * blockDim.x + threadIdx.x) >> 5;
    if (gw >= BB*HH*LL) return;
    int lane = threadIdx.x & 31;
    int l  = gw & (LL-1);
    int bh = gw >> 11;
    int b = bh >> 3, h = bh & 7;
    int grp = lane >> 3, lg = lane & 7;

    const float* qrow = Q + (((size_t)b*LL + l)*HH + h)*DD;
    float4 q0 = *(const float4*)(qrow + lg*8);
    float4 q1 = *(const float4*)(qrow + lg*8 + 4);

    const int* irow = idx + l*SS;
    float vmax = -CUDART_INF_F, vsum = 0.f;

    #pragma unroll 5
    for (int it = 0; it < SS/4; ++it) {
        int j = irow[it*4 + grp];
        const float* krow = K + (((size_t)b*LL + j)*HH + h)*DD + lg*8;
        float4 k0 = *(const float4*)(krow);
        float4 k1 = *(const float4*)(krow + 4);
        float p = q0.x*k0.x + q0.y*k0.y + q0.z*k0.z + q0.w*k0.w
                + q1.x*k1.x + q1.y*k1.y + q1.z*k1.z + q1.w*k1.w;
        p += __shfl_xor_sync(0xffffffffu, p, 4);
        p += __shfl_xor_sync(0xffffffffu, p, 2);
        p += __shfl_xor_sync(0xffffffffu, p, 1);
        vmax = fmaxf(vmax, p);
        vsum += p;
    }
    vmax = fmaxf(vmax, __shfl_xor_sync(0xffffffffu, vmax, 8));
    vmax = fmaxf(vmax, __shfl_xor_sync(0xffffffffu, vmax, 16));
    vsum += __shfl_xor_sync(0xffffffffu, vsum, 8);
    vsum += __shfl_xor_sync(0xffffffffu, vsum, 16);
    if (lane == 0) g_M[gw] = vmax - vsum * (1.0f/(float)LL);
}

// ---------------------------------------------------------------------------
// Kernel 2: per-(b,h) top-80 of M (iterative argmax, smaller index on ties),
// then replay the clipped scatter (last-wins) to build the winner list.
// ---------------------------------------------------------------------------
__global__ void k_topk() {
    int bh = blockIdx.x;
    __shared__ float sm[LL];
    __shared__ float rv[8];
    __shared__ int   ri[8];
    __shared__ int   stop[UU];
    __shared__ int   win[UU];
    int t = threadIdx.x, lane = t & 31, warp = t >> 5;

    for (int i = t; i < LL; i += 256) sm[i] = g_M[bh*LL + i];
    __syncthreads();

    for (int u = 0; u < UU; ++u) {
        float best = -CUDART_INF_F; int bi = LL;
        for (int i = t; i < LL; i += 256) {
            float v = sm[i];
            if (v > best) { best = v; bi = i; }
        }
        #pragma unroll
        for (int o = 16; o; o >>= 1) {
            float ov = __shfl_xor_sync(0xffffffffu, best, o);
            int   oi = __shfl_xor_sync(0xffffffffu, bi, o);
            if (ov > best || (ov == best && oi < bi)) { best = ov; bi = oi; }
        }
        if (lane == 0) { rv[warp] = best; ri[warp] = bi; }
        __syncthreads();
        if (t == 0) {
            float m = rv[0]; int mi = ri[0];
            for (int w = 1; w < 8; ++w)
                if (rv[w] > m || (rv[w] == m && ri[w] < mi)) { m = rv[w]; mi = ri[w]; }
            stop[u] = mi;
            sm[mi] = -CUDART_INF_F;
        }
        __syncthreads();
    }

    if (t < UU) win[t] = -1;
    __syncthreads();
    if (t == 0) {
        for (int u = 0; u < UU; ++u) { int jj = min(stop[u], UU-1); win[jj] = u; }
        int n = 0;
        for (int jj = 0; jj < UU; ++jj) {
            if (win[jj] >= 0) {
                g_wl[bh*UU + n] = stop[win[jj]];
                g_wj[bh*UU + n] = jj;
                n++;
            }
        }
        g_nw[bh] = n;
    }
}

// ---------------------------------------------------------------------------
// Kernel 3a: V partial sums, grid (bh, VSPLIT) — parallel over key chunks.
// ---------------------------------------------------------------------------
__global__ void k_vpart(const float* __restrict__ V) {
    int bh = blockIdx.x, sp = blockIdx.y;
    int b = bh >> 3, h = bh & 7;
    int t = threadIdx.x, grp = t >> 6, d = t & 63;
    __shared__ float ac[4][64];
    int k0 = sp * VCHUNK;
    float s = 0.f;
    #pragma unroll 8
    for (int kk = grp; kk < VCHUNK; kk += 4)
        s += V[(((size_t)b*LL + k0 + kk)*HH + h)*DD + d];
    ac[grp][d] = s;
    __syncthreads();
    if (t < 64)
        g_vpart[(bh*VSPLIT + sp)*DD + t] = ac[0][t] + ac[1][t] + ac[2][t] + ac[3][t];
}

// ---------------------------------------------------------------------------
// Kernel 3b: combine V partials -> mean, broadcast-fill all 80 output rows.
// ---------------------------------------------------------------------------
__global__ void k_fill(float* __restrict__ out) {
    int bh = blockIdx.x; int b = bh >> 3, h = bh & 7;
    int t = threadIdx.x;
    __shared__ float mean[64];
    if (t < 64) {
        float s = 0.f;
        #pragma unroll
        for (int i = 0; i < VSPLIT; ++i) s += g_vpart[(bh*VSPLIT + i)*DD + t];
        mean[t] = s * (1.0f/(float)LL);
    }
    __syncthreads();
    for (int e = t; e < UU*64; e += 256) {
        int j = e >> 6, d = e & 63;
        out[(((size_t)b*UU + j)*HH + h)*DD + d] = mean[d];
    }
}

// ---------------------------------------------------------------------------
// Kernel 4a: split-K attention partials for winner rows only.
// grid (bh, u, split); blocks with u >= g_nw[bh] exit.
// ---------------------------------------------------------------------------
__global__ void k_attn_part(const float* __restrict__ Q, const float* __restrict__ K,
                            const float* __restrict__ V) {
    int bh = blockIdx.x;
    if ((int)blockIdx.y >= g_nw[bh]) return;
    int u = blockIdx.y, sp = blockIdx.z;
    int b = bh >> 3, h = bh & 7;
    int l = g_wl[bh*UU + u];
    int k0 = sp * CHUNK;

    __shared__ float q[DD];
    __shared__ float p[CHUNK];
    __shared__ float red[8];
    __shared__ float ac[4][64];
    int t = threadIdx.x, lane = t & 31, warp = t >> 5;

    if (t < DD) q[t] = Q[(((size_t)b*LL + l)*HH + h)*DD + t];
    __syncthreads();
    float q0 = q[lane*2], q1 = q[lane*2+1];

    // scores for this chunk: 8 warps x 16 keys
    float lmax = -CUDART_INF_F;
    #pragma unroll 4
    for (int kk = warp; kk < CHUNK; kk += 8) {
        float2 kv = *(const float2*)(K + (((size_t)b*LL + k0 + kk)*HH + h)*DD + lane*2);
        float s = q0*kv.x + q1*kv.y;
        #pragma unroll
        for (int o = 16; o; o >>= 1) s += __shfl_xor_sync(0xffffffffu, s, o);
        s *= 0.125f;                 // 1/sqrt(64)
        if (lane == 0) p[kk] = s;
        lmax = fmaxf(lmax, s);
    }
    if (lane == 0) red[warp] = lmax;
    __syncthreads();                 // publishes p[] and red[]
    if (t == 0) { float m = red[0]; for (int w = 1; w < 8; ++w) m = fmaxf(m, red[w]); red[0] = m; }
    __syncthreads();
    float m = red[0];
    __syncthreads();                 // all have read red[0] before reuse

    float ls = 0.f;
    if (t < CHUNK) { float e = __expf(p[t] - m); p[t] = e; ls = e; }
    #pragma unroll
    for (int o = 16; o; o >>= 1) ls += __shfl_xor_sync(0xffffffffu, ls, o);
    if (lane == 0) red[warp] = ls;
    __syncthreads();                 // publishes exp'd p[] and warp sums
    float ssum = red[0]+red[1]+red[2]+red[3]+red[4]+red[5]+red[6]+red[7];

    // partial PV: 4 key-groups x 64 d-threads, coalesced V reads
    int grp = t >> 6, d = t & 63;
    float acc = 0.f;
    #pragma unroll 8
    for (int kk = grp; kk < CHUNK; kk += 4)
        acc += p[kk] * V[(((size_t)b*LL + k0 + kk)*HH + h)*DD + d];
    ac[grp][d] = acc;
    __syncthreads();
    int base = (bh*UU + u)*SPLIT + sp;
    if (t < 64)
        g_pv[(size_t)base*DD + t] = ac[0][t] + ac[1][t] + ac[2][t] + ac[3][t];
    if (t == 0) { g_pmax[base] = m; g_psum[base] = ssum; }
}

// ---------------------------------------------------------------------------
// Kernel 4b: combine split partials (max-rescale), normalize, write winners.
// ---------------------------------------------------------------------------
__global__ void k_attn_comb(float* __restrict__ out) {
    int bh = blockIdx.x;
    if ((int)blockIdx.y >= g_nw[bh]) return;
    int u = blockIdx.y;
    int b = bh >> 3, h = bh & 7;
    int j = g_wj[bh*UU + u];
    int t = threadIdx.x;                 // 64 threads
    int base = (bh*UU + u)*SPLIT;

    float m = -CUDART_INF_F;
    #pragma unroll
    for (int i = 0; i < SPLIT; ++i) m = fmaxf(m, g_pmax[base + i]);
    float s = 0.f, pv = 0.f;
    #pragma unroll
    for (int i = 0; i < SPLIT; ++i) {
        float w = __expf(g_pmax[base + i] - m);
        s  += g_psum[base + i] * w;
        pv += g_pv[(size_t)(base + i)*DD + t] * w;
    }
    out[(((size_t)b*UU + j)*HH + h)*DD + t] = pv / s;
}

// ---------------------------------------------------------------------------
extern "C" void kernel_launch(void* const* d_in, const int* in_sizes, int n_in,
                              void* d_out, int out_size) {
    const float* Q   = (const float*)d_in[0];
    const float* K   = (const float*)d_in[1];
    const float* V   = (const float*)d_in[2];
    const int*   idx = (const int*)d_in[3];
    float* out = (float*)d_out;

    k_sample<<<(BB*HH*LL)/8, 256>>>(Q, K, idx);
    k_topk<<<BHN, 256>>>();
    dim3 gv(BHN, VSPLIT);
    k_vpart<<<gv, 256>>>(V);
    k_fill<<<BHN, 256>>>(out);
    dim3 ga(BHN, UU, SPLIT);
    k_attn_part<<<ga, 256>>>(Q, K, V);
    dim3 gc(BHN, UU);
    k_attn_comb<<<gc, 64>>>(out);
}